// round 14
// baseline (speedup 1.0000x reference)
#include <cuda_runtime.h>
#include <cuda_fp16.h>
#include <cstdint>

// ===========================================================================
// Fixed shapes: B=1, N1=512, N2=2048, C=1024, H=8, hd=128
// All GEMMs: mma.sync m16n8k16 fp16, fp32 acc, 1-term (A hi * B hi).
// Two-stream fork/join; TM=32 tiles for small-grid GEMMs.
// ===========================================================================

constexpr size_t Mi = 1024 * 1024;

// ------------------------- fp32 scratch layout ------------------------------
constexpr size_t F_QC   = 0;                 // [512,1024] x2
constexpr size_t F_KVC  = F_QC   + Mi;       // [2048,2048] x2 (k|v cols)
constexpr size_t F_SCC  = F_KVC  + 8 * Mi;   // [8,512,2048] x2
constexpr size_t F_SCR  = F_SCC  + 8 * Mi;
constexpr size_t F_SIMC = F_SCR  + 8 * Mi;
constexpr size_t F_SIMR = F_SIMC + Mi;
constexpr size_t F_BIAS = F_SIMR + Mi;
constexpr size_t F_TOTAL = F_BIAS + 4096;
__device__ float g_scratch[F_TOTAL];

// ------------------------- fp16 plane layout --------------------------------
constexpr size_t HXCH  = 0;                  // x hi [2048,1024] x2
constexpr size_t HWQH  = HXCH  + 4 * Mi;     // WqT hi [1024,1024] x2
constexpr size_t HWKH  = HWQH  + 2 * Mi;     // WkvT hi [2048,1024] x2
constexpr size_t HWLH  = HWKH  + 4 * Mi;     // WlinT hi [2048,2048] x2
constexpr size_t HQH   = HWLH  + 8 * Mi;     // q norm hi [512,1024] x2
constexpr size_t HKH   = HQH   + 1 * Mi;     // k norm hi [2048,1024] x2
constexpr size_t HVNH  = HKH   + 4 * Mi;     // v norm hi [2048,1024] x2
constexpr size_t HVTH  = HVNH  + 4 * Mi;     // vT hi [1024,2048] x2
constexpr size_t HATH  = HVTH  + 4 * Mi;     // attn hi [8,512,2048]
constexpr size_t HS2H  = HATH  + 8 * Mi;     // s2 hi [512,2048]
constexpr size_t HOWH  = HS2H  + Mi;         // ow hi [512,2048]
constexpr size_t HXCCH = HOWH  + Mi;         // concat hi [512,2048] x2
constexpr size_t H_TOTAL = HXCCH + 2 * Mi;
__device__ __half g_half[H_TOTAL];

// ----------------------------- helpers --------------------------------------
__device__ __forceinline__ uint32_t smem_u32(const void* p) {
    uint32_t a;
    asm("{ .reg .u64 t; cvta.to.shared.u64 t, %1; cvt.u32.u64 %0, t; }"
        : "=r"(a) : "l"(p));
    return a;
}
__device__ __forceinline__ uint32_t pack2(__half a, __half b) {
    __half2 h = __halves2half2(a, b);
    return *(uint32_t*)&h;
}
__device__ __forceinline__ void ldsm4(uint32_t* r, uint32_t addr) {
    asm volatile("ldmatrix.sync.aligned.m8n8.x4.shared.b16 {%0,%1,%2,%3}, [%4];"
                 : "=r"(r[0]), "=r"(r[1]), "=r"(r[2]), "=r"(r[3]) : "r"(addr));
}
__device__ __forceinline__ void mma16816(float* d, const uint32_t* a, const uint32_t* b) {
    asm volatile("mma.sync.aligned.m16n8k16.row.col.f32.f16.f16.f32 "
                 "{%0,%1,%2,%3}, {%4,%5,%6,%7}, {%8,%9}, {%0,%1,%2,%3};"
                 : "+f"(d[0]), "+f"(d[1]), "+f"(d[2]), "+f"(d[3])
                 : "r"(a[0]), "r"(a[1]), "r"(a[2]), "r"(a[3]),
                   "r"(b[0]), "r"(b[1]));
}
__device__ __forceinline__ void cp16(uint32_t dst, const void* src) {
    asm volatile("cp.async.cg.shared.global [%0], [%1], 16;"
                 :: "r"(dst), "l"(src));
}
#define CP_COMMIT() asm volatile("cp.async.commit_group;" ::: "memory")
#define CP_WAIT1() asm volatile("cp.async.wait_group 1;" ::: "memory")
#define CP_WAIT0() asm volatile("cp.async.wait_group 0;" ::: "memory")

__device__ __forceinline__ uint32_t swz(int row, int chunk) {
    return (uint32_t)row * 64u + (uint32_t)((chunk ^ ((row >> 1) & 3)) << 4);
}

// ------------------------------- hgemm (NT) ----------------------------------
// C[M,N] = Ah[M,K] * Bh[N,K]^T. CTA TMx128x32, 4 warps ((TM/WM)x2, WM=TM/2).
template <int TM, bool BIAS, bool FOUT, bool SPLITOUT>
__global__ void __launch_bounds__(128, 3)
hgemm(const __half* __restrict__ Ah_g, const __half* __restrict__ Bh_g,
      const float* __restrict__ bias,
      float* C, __half* Chi,
      int K, int lda, int ldb, int ldc, int z1n,
      long long a_s1, long long a_s2, long long b_s1, long long b_s2,
      long long c_s1, long long c_s2, long long bias_s)
{
    constexpr int TN = 128;
    constexpr int ASZ = TM * 64;
    constexpr int BSZ = TN * 64;
    constexpr int STAGE = ASZ + BSZ;
    constexpr int WM = TM / 2;
    constexpr int MI = WM / 16;             // 2 (TM=64) or 1 (TM=32)
    constexpr int NB = 4, NJ = 8;

    extern __shared__ char dsm[];
    const uint32_t sb = smem_u32(dsm);
    const int tid = threadIdx.x;

    const int z1 = blockIdx.z % z1n, z2 = blockIdx.z / z1n;
    const long long aoff = (long long)z1 * a_s1 + (long long)z2 * a_s2 +
                           (long long)blockIdx.y * TM * lda;
    const long long boff = (long long)z1 * b_s1 + (long long)z2 * b_s2 +
                           (long long)blockIdx.x * TN * ldb;
    const long long coff = (long long)z1 * c_s1 + (long long)z2 * c_s2;
    Ah_g += aoff;
    Bh_g += boff;
    if (FOUT) C += coff;
    if (SPLITOUT) Chi += coff;
    if (BIAS) bias += z1 * bias_s;

    const int lrow = tid >> 2;        // 0..31
    const int lc16 = tid & 3;

    const int lane = tid & 31, w = tid >> 5;
    const int wm = (w >> 1) * WM;
    const int wn = (w & 1) * 64;
    const int g = lane >> 3, r = lane & 7;
    const int a_r  = r + ((g & 1) << 3);
    const int a_kc = g >> 1;
    const int b_r  = r + ((g >> 1) << 3);
    const int b_kc = g & 1;

    float acc[MI][NJ][4];
#pragma unroll
    for (int i = 0; i < MI; i++)
#pragma unroll
        for (int j = 0; j < NJ; j++)
#pragma unroll
            for (int e = 0; e < 4; e++) acc[i][j][e] = 0.f;

    auto LOADA = [&](int k0, int s) {
        const uint32_t base = sb + (uint32_t)s * STAGE;
#pragma unroll
        for (int j = 0; j < TM / 32; j++) {
            int row = lrow + j * 32;
            uint32_t so = swz(row, lc16);
            cp16(base + so, Ah_g + (size_t)row * lda + k0 + lc16 * 8);
        }
#pragma unroll
        for (int j = 0; j < TN / 32; j++) {
            int row = lrow + j * 32;
            uint32_t so = swz(row, lc16);
            cp16(base + ASZ + so, Bh_g + (size_t)row * ldb + k0 + lc16 * 8);
        }
        CP_COMMIT();
    };

    auto COMPUTE = [&](int s) {
        const uint32_t base = sb + (uint32_t)s * STAGE;
        const uint32_t bA = base, bB = base + ASZ;
#pragma unroll
        for (int ks = 0; ks < 2; ks++) {
            const int kc = ks * 2;
            uint32_t ah[4 * MI], bh[4 * NB];
#pragma unroll
            for (int i = 0; i < MI; i++)
                ldsm4(&ah[4 * i], bA + swz(wm + i * 16 + a_r, kc + a_kc));
#pragma unroll
            for (int t = 0; t < NB; t++)
                ldsm4(&bh[4 * t], bB + swz(wn + t * 16 + b_r, kc + b_kc));
#pragma unroll
            for (int i = 0; i < MI; i++)
#pragma unroll
                for (int j = 0; j < NJ; j++)
                    mma16816(acc[i][j], &ah[4 * i], &bh[2 * j]);
        }
    };

    const int T = K >> 5;
    LOADA(0, 0);
    for (int t = 0; t < T; t++) {
        if (t + 1 < T) {
            LOADA((t + 1) << 5, (t + 1) & 1);
            CP_WAIT1();
        } else {
            CP_WAIT0();
        }
        __syncthreads();
        COMPUTE(t & 1);
        __syncthreads();
    }

    const int rbase = blockIdx.y * TM + wm;
    const int cbase = blockIdx.x * TN + wn;
#pragma unroll
    for (int i = 0; i < MI; i++) {
#pragma unroll
        for (int j = 0; j < NJ; j++) {
            int row0 = rbase + i * 16 + (lane >> 2);
            int col = cbase + j * 8 + ((lane & 3) << 1);
            float2 v0 = {acc[i][j][0], acc[i][j][1]};
            float2 v1 = {acc[i][j][2], acc[i][j][3]};
            if (BIAS) {
                float2 b2 = *(const float2*)(bias + col);
                v0.x += b2.x; v0.y += b2.y;
                v1.x += b2.x; v1.y += b2.y;
            }
            if (FOUT) {
                *(float2*)(C + (size_t)row0 * ldc + col) = v0;
                *(float2*)(C + (size_t)(row0 + 8) * ldc + col) = v1;
            }
            if (SPLITOUT) {
                *(uint32_t*)(Chi + (size_t)row0 * ldc + col) =
                    pack2(__float2half_rn(v0.x), __float2half_rn(v0.y));
                *(uint32_t*)(Chi + (size_t)(row0 + 8) * ldc + col) =
                    pack2(__float2half_rn(v1.x), __float2half_rn(v1.y));
            }
        }
    }
}

// ------------- transpose + convert to fp16 (hi), dual source -----------------
__global__ void __launch_bounds__(256)
transpose_convert2(const float* __restrict__ in0, const float* __restrict__ in1,
                   __half* __restrict__ hi, int ldin, int ldout, long long dst_bs)
{
    const float* in = blockIdx.z ? in1 : in0;
    hi += blockIdx.z * dst_bs;
    __shared__ float t[32][33];
    const int bx = blockIdx.x * 32, by = blockIdx.y * 32;
    const int x = threadIdx.x, y = threadIdx.y;
#pragma unroll
    for (int j = 0; j < 32; j += 8)
        t[y + j][x] = in[(size_t)(by + y + j) * ldin + bx + x];
    __syncthreads();
#pragma unroll
    for (int j = 0; j < 32; j += 8) {
        size_t o = (size_t)(bx + y + j) * ldout + by + x;
        hi[o] = __float2half_rn(t[x][y + j]);
    }
}

// ------------------ plain convert to fp16 (hi), dual source ------------------
__global__ void __launch_bounds__(256)
convert2_f16(const float* __restrict__ in0, const float* __restrict__ in1,
             __half* __restrict__ hi, int n4, long long dst_bs)
{
    const float* in = blockIdx.y ? in1 : in0;
    hi += blockIdx.y * dst_bs;
    int i = blockIdx.x * 256 + threadIdx.x;
    if (i >= n4) return;
    float4 v = ((const float4*)in)[i];
    uint2 h;
    h.x = pack2(__float2half_rn(v.x), __float2half_rn(v.y));
    h.y = pack2(__float2half_rn(v.z), __float2half_rn(v.w));
    ((uint2*)hi)[i] = h;
}

// -------------------- L2 normalize (per head) -> fp16 hi ----------------------
__global__ void __launch_bounds__(256)
l2norm_h(const float* __restrict__ src, __half* __restrict__ hi,
         int lds, int ldd, int nvec, long long src_bs, long long dst_bs)
{
    src += blockIdx.y * src_bs;
    hi += blockIdx.y * dst_bs;
    int vec = blockIdx.x * 8 + (threadIdx.x >> 5);
    int lane = threadIdx.x & 31;
    if (vec >= nvec) return;
    int row = vec >> 3, h = vec & 7;
    const float* s = src + (size_t)row * lds + h * 128 + lane * 4;
    float4 v = *(const float4*)s;
    float ss = v.x * v.x + v.y * v.y + v.z * v.z + v.w * v.w;
#pragma unroll
    for (int o = 16; o; o >>= 1) ss += __shfl_xor_sync(0xffffffffu, ss, o);
    float inv = 1.0f / sqrtf(ss);
    uint2 hh;
    hh.x = pack2(__float2half_rn(v.x * inv), __float2half_rn(v.y * inv));
    hh.y = pack2(__float2half_rn(v.z * inv), __float2half_rn(v.w * inv));
    *(uint2*)(hi + (size_t)row * ldd + h * 128 + lane * 4) = hh;
}

// ------------------------------ block reductions -----------------------------
static __device__ __forceinline__ float blockReduceMax(float v) {
    __shared__ float s[8];
#pragma unroll
    for (int o = 16; o; o >>= 1) v = fmaxf(v, __shfl_xor_sync(0xffffffffu, v, o));
    if ((threadIdx.x & 31) == 0) s[threadIdx.x >> 5] = v;
    __syncthreads();
    v = s[threadIdx.x & 7];
#pragma unroll
    for (int o = 4; o; o >>= 1) v = fmaxf(v, __shfl_xor_sync(0xffffffffu, v, o));
    __syncthreads();
    return v;
}
static __device__ __forceinline__ float blockReduceSum(float v) {
    __shared__ float s[8];
#pragma unroll
    for (int o = 16; o; o >>= 1) v += __shfl_xor_sync(0xffffffffu, v, o);
    if ((threadIdx.x & 31) == 0) s[threadIdx.x >> 5] = v;
    __syncthreads();
    v = s[threadIdx.x & 7];
#pragma unroll
    for (int o = 4; o; o >>= 1) v += __shfl_xor_sync(0xffffffffu, v, o);
    __syncthreads();
    return v;
}

// --------- softmax blend, one block per (q, head), write attn hi -------------
__global__ void __launch_bounds__(256)
softmax_combine2(const float* __restrict__ sc_cls, const float* __restrict__ sc_reg,
                 const float* __restrict__ cls_score, __half* __restrict__ attn_h)
{
    const int q = blockIdx.x, h = blockIdx.y;
    const int tid = threadIdx.x;
    const float* pc = sc_cls + ((size_t)h * 512 + q) * 2048;
    const float* pr = sc_reg + ((size_t)h * 512 + q) * 2048;
    float c[8], r[8];
    float mc = -1e30f, mr = -1e30f;
#pragma unroll
    for (int j = 0; j < 8; j++) {
        int k = j * 256 + tid;
        c[j] = pc[k] * 25.0f * cls_score[k];
        r[j] = pr[k] * 25.0f;
        mc = fmaxf(mc, c[j]);
        mr = fmaxf(mr, r[j]);
    }
    mc = blockReduceMax(mc);
    mr = blockReduceMax(mr);
    float sc = 0.f, sr = 0.f;
#pragma unroll
    for (int j = 0; j < 8; j++) {
        c[j] = expf(c[j] - mc);
        r[j] = expf(r[j] - mr);
        sc += c[j];
        sr += r[j];
    }
    sc = blockReduceSum(sc);
    sr = blockReduceSum(sr);
    float ic = 0.5f / sc, ir = 0.5f / sr;
    __half* pa = attn_h + ((size_t)h * 512 + q) * 2048;
#pragma unroll
    for (int j = 0; j < 8; j++)
        pa[j * 256 + tid] = __float2half_rn(c[j] * ic + r[j] * ir);
}

// ----- masked renormalized second-round weights; asum recomputed from attn ---
__global__ void __launch_bounds__(256)
mask_renorm(const __half* __restrict__ attn_h, const float* __restrict__ simc,
            const float* __restrict__ simr,
            __half* __restrict__ s2h, __half* __restrict__ owh)
{
    const int q = blockIdx.x;
    const int tid = threadIdx.x;
    float a[8];
    float mx = -1e30f;
#pragma unroll
    for (int j = 0; j < 8; j++) {
        int k = j * 256 + tid;
        float s = 0.f;
#pragma unroll
        for (int h = 0; h < 8; h++)
            s += __half2float(attn_h[((size_t)h * 512 + q) * 2048 + k]);
        a[j] = s * 0.125f;
        mx = fmaxf(mx, a[j]);
    }
    mx = blockReduceMax(mx);
    float sum = 0.f;
#pragma unroll
    for (int j = 0; j < 8; j++) {
        a[j] = expf(a[j] - mx);
        sum += a[j];
    }
    sum = blockReduceSum(sum);
    float inv = 1.0f / sum;
    float sm = 0.f;
#pragma unroll
    for (int j = 0; j < 8; j++) {
        int k = j * 256 + tid;
        float m = (simc[(size_t)q * 2048 + k] * 0.125f > 0.75f) ? 1.0f : 0.0f;
        a[j] = a[j] * inv * m;
        sm += a[j];
    }
    sm = blockReduceSum(sm);
    inv = 1.0f / sm;
    float so = 0.f;
    float o[8];
#pragma unroll
    for (int j = 0; j < 8; j++) {
        int k = j * 256 + tid;
        a[j] *= inv;
        s2h[(size_t)q * 2048 + k] = __float2half_rn(a[j]);
        float m = (simr[(size_t)q * 2048 + k] * 0.125f > 0.99f) ? 1.0f : 0.0f;
        o[j] = a[j] * m;
        so += o[j];
    }
    so = blockReduceSum(so);
    inv = 1.0f / so;
#pragma unroll
    for (int j = 0; j < 8; j++)
        owh[(size_t)q * 2048 + j * 256 + tid] = __float2half_rn(o[j] * inv);
}

// -------------------- copy x_ori into concat (hi only) -----------------------
__global__ void __launch_bounds__(256)
copy_xori(const float* __restrict__ kv, __half* __restrict__ xh)
{
    int z = blockIdx.y;
    kv += (size_t)z * 4 * Mi;
    xh += (size_t)z * Mi;
    int idx = blockIdx.x * 256 + threadIdx.x;
    int q = idx >> 8;
    int c4 = idx & 255;
    size_t off = (size_t)q * 2048 + 1024 + (size_t)c4 * 4;
    float4 v = *(const float4*)(kv + off);
    *(uint32_t*)(xh + off) = pack2(__float2half_rn(v.x), __float2half_rn(v.y));
    *(uint32_t*)(xh + off + 2) = pack2(__float2half_rn(v.z), __float2half_rn(v.w));
}

// ------------------------------ bias copy ------------------------------------
__global__ void copy_bias(const float* __restrict__ b0, const float* __restrict__ b1,
                          float* __restrict__ dst)
{
    int i = blockIdx.x * 256 + threadIdx.x;
    if (i < 2048) { dst[i] = b0[i]; dst[2048 + i] = b1[i]; }
}

// --------------------------------- launch ------------------------------------
extern "C" void kernel_launch(void* const* d_in, const int* in_sizes, int n_in,
                              void* d_out, int out_size)
{
    const float* x_cls     = (const float*)d_in[0];
    const float* x_reg     = (const float*)d_in[1];
    const float* cls_score = (const float*)d_in[2];
    const float* W_q_cls   = (const float*)d_in[4];
    const float* W_kv_cls  = (const float*)d_in[5];
    const float* W_q_reg   = (const float*)d_in[6];
    const float* W_kv_reg  = (const float*)d_in[7];
    const float* W_lin     = (const float*)d_in[8];
    const float* b_lin     = (const float*)d_in[9];
    const float* W_lin_reg = (const float*)d_in[10];
    const float* b_lin_reg = (const float*)d_in[11];
    float* out = (float*)d_out;

    float* F = nullptr;
    __half* Hp = nullptr;
    cudaGetSymbolAddress((void**)&F, g_scratch);
    cudaGetSymbolAddress((void**)&Hp, g_half);

    float* qc   = F + F_QC;
    float* kvc  = F + F_KVC;
    float* scc  = F + F_SCC;
    float* scr  = F + F_SCR;
    float* simc = F + F_SIMC;
    float* simr = F + F_SIMR;
    float* bias2 = F + F_BIAS;

    constexpr int SM64 = 2 * (4096 + 8192);  // 24576
    constexpr int SM32 = 2 * (2048 + 8192);  // 20480

    auto g64   = hgemm<64, false, true, false>;
    auto g32f  = hgemm<32, false, true, false>;
    auto g32s  = hgemm<32, false, false, true>;
    auto g32b  = hgemm<32, true, true, false>;
    cudaFuncSetAttribute(g64, cudaFuncAttributeMaxDynamicSharedMemorySize, SM64);
    cudaFuncSetAttribute(g32f, cudaFuncAttributeMaxDynamicSharedMemorySize, SM32);
    cudaFuncSetAttribute(g32s, cudaFuncAttributeMaxDynamicSharedMemorySize, SM32);
    cudaFuncSetAttribute(g32b, cudaFuncAttributeMaxDynamicSharedMemorySize, SM32);

    static bool s_init = false;
    static cudaStream_t sB;
    static cudaEvent_t eFork, eX, eQ, eVT, eXori, eSoft, eEnd;
    if (!s_init) {
        cudaStreamCreateWithFlags(&sB, cudaStreamNonBlocking);
        cudaEventCreateWithFlags(&eFork, cudaEventDisableTiming);
        cudaEventCreateWithFlags(&eX, cudaEventDisableTiming);
        cudaEventCreateWithFlags(&eQ, cudaEventDisableTiming);
        cudaEventCreateWithFlags(&eVT, cudaEventDisableTiming);
        cudaEventCreateWithFlags(&eXori, cudaEventDisableTiming);
        cudaEventCreateWithFlags(&eSoft, cudaEventDisableTiming);
        cudaEventCreateWithFlags(&eEnd, cudaEventDisableTiming);
        s_init = true;
    }
    cudaStream_t sA = 0;

    dim3 tb(32, 8);
    const long long OSTR = 512LL * 3072;

    // ===== fork =====
    cudaEventRecord(eFork, sA);
    cudaStreamWaitEvent(sB, eFork, 0);

    // --- sA: x converts + Wkv transpose ---
    convert2_f16<<<dim3(2048, 2), 256, 0, sA>>>(x_cls, x_reg, Hp + HXCH,
                                                2048 * 256, 2 * Mi);
    transpose_convert2<<<dim3(64, 32, 2), tb, 0, sA>>>(W_kv_cls, W_kv_reg,
                                                       Hp + HWKH, 2048, 1024, 2 * Mi);
    cudaEventRecord(eX, sA);

    // --- sA: k projection (WkvT rows [0,1024)) -> l2norm k ---
    g64<<<dim3(8, 32, 2), 128, SM64, sA>>>(
        Hp + HXCH, Hp + HWKH, nullptr,
        kvc, nullptr, 1024, 1024, 1024, 2048,
        2, 2 * Mi, 0, 2 * Mi, 0, 4 * Mi, 0, 0);
    l2norm_h<<<dim3(2048, 2), 256, 0, sA>>>(kvc, Hp + HKH,
                                            2048, 1024, 2048 * 8, 4 * Mi, 2 * Mi);

    // --- sB: Wq/Wlin transposes + bias -> q projection + l2norm q ---
    transpose_convert2<<<dim3(32, 32, 2), tb, 0, sB>>>(W_q_cls, W_q_reg,
                                                       Hp + HWQH, 1024, 1024, Mi);
    transpose_convert2<<<dim3(64, 64, 2), tb, 0, sB>>>(W_lin, W_lin_reg,
                                                       Hp + HWLH, 2048, 2048, 4 * Mi);
    copy_bias<<<8, 256, 0, sB>>>(b_lin, b_lin_reg, bias2);
    cudaStreamWaitEvent(sB, eX, 0);
    g32f<<<dim3(8, 16, 2), 128, SM32, sB>>>(
        Hp + HXCH, Hp + HWQH, nullptr,
        qc, nullptr, 1024, 1024, 1024, 1024,
        2, 2 * Mi, 0, Mi, 0, Mi / 2, 0, 0);
    l2norm_h<<<dim3(512, 2), 256, 0, sB>>>(qc, Hp + HQH,
                                           1024, 1024, 512 * 8, Mi / 2, Mi / 2);
    cudaEventRecord(eQ, sB);

    // --- sB: v projection + v norm + vT + xori + sims ---
    g64<<<dim3(8, 32, 2), 128, SM64, sB>>>(
        Hp + HXCH, Hp + HWKH + Mi, nullptr,
        kvc + 1024, nullptr, 1024, 1024, 1024, 2048,
        2, 2 * Mi, 0, 2 * Mi, 0, 4 * Mi, 0, 0);
    l2norm_h<<<dim3(2048, 2), 256, 0, sB>>>(kvc + 1024, Hp + HVNH,
                                            2048, 1024, 2048 * 8, 4 * Mi, 2 * Mi);
    transpose_convert2<<<dim3(32, 64, 2), tb, 0, sB>>>(kvc + 1024, kvc + 4 * Mi + 1024,
                                                       Hp + HVTH, 2048, 2048, 2 * Mi);
    cudaEventRecord(eVT, sB);
    copy_xori<<<dim3(512, 2), 256, 0, sB>>>(kvc, Hp + HXCCH);
    cudaEventRecord(eXori, sB);
    g64<<<dim3(16, 8, 2), 128, SM64, sB>>>(
        Hp + HVNH, Hp + HVNH, nullptr,
        simc, nullptr, 1024, 1024, 1024, 2048,
        2, 2 * Mi, 0, 2 * Mi, 0, Mi, 0, 0);

    // --- sA: scores (needs q) -> softmax ---
    cudaStreamWaitEvent(sA, eQ, 0);
    g64<<<dim3(16, 8, 16), 128, SM64, sA>>>(
        Hp + HQH, Hp + HKH, nullptr,
        scc, nullptr, 128, 1024, 1024, 2048,
        8, 128, Mi / 2, 128, 2 * Mi, Mi, 8 * Mi, 0);
    softmax_combine2<<<dim3(512, 8), 256, 0, sA>>>(scc, scr, cls_score, Hp + HATH);
    cudaEventRecord(eSoft, sA);

    // --- sA: attn@v (needs vT) -> out-linears (needs xori) ---
    cudaStreamWaitEvent(sA, eVT, 0);
    g32s<<<dim3(1, 16, 16), 128, SM32, sA>>>(
        Hp + HATH, Hp + HVTH, nullptr,
        nullptr, Hp + HXCCH, 2048, 2048, 2048, 2048,
        8, Mi, 0, 128LL * 2048, 2 * Mi, 128, Mi, 0);
    cudaStreamWaitEvent(sA, eXori, 0);
    g32b<<<dim3(16, 16, 2), 128, SM32, sA>>>(
        Hp + HXCCH, Hp + HWLH, bias2,
        out + 1024, nullptr, 2048, 2048, 2048, 3072,
        2, Mi, 0, 4 * Mi, 0, OSTR, 0, 2048);

    // --- sB: mask_renorm (needs attn + sims) -> support ---
    cudaStreamWaitEvent(sB, eSoft, 0);
    mask_renorm<<<512, 256, 0, sB>>>(Hp + HATH, simc, simr, Hp + HS2H, Hp + HOWH);
    g32f<<<dim3(8, 16, 2), 128, SM32, sB>>>(
        Hp + HS2H, Hp + HVTH, nullptr,
        out, nullptr, 2048, 2048, 2048, 3072,
        2, Mi, 0, 2 * Mi, 0, OSTR, 0, 0);
    cudaEventRecord(eEnd, sB);

    // ===== join =====
    cudaStreamWaitEvent(sA, eEnd, 0);
}

// round 15
// speedup vs baseline: 1.1152x; 1.1152x over previous
#include <cuda_runtime.h>
#include <cuda_fp16.h>
#include <cstdint>

// ===========================================================================
// Fixed shapes: B=1, N1=512, N2=2048, C=1024, H=8, hd=128
// All GEMMs: mma.sync m16n8k16 fp16, fp32 acc, 1-term. TM=64 tiles.
// k-proj/q-proj write fp16 directly; fp16-input L2 norms.
// Two-stream fork/join (graph-capture-safe).
// ===========================================================================

constexpr size_t Mi = 1024 * 1024;

// ------------------------- fp32 scratch layout ------------------------------
constexpr size_t F_KVC  = 0;                 // [2048,2048] x2 (v in cols 1024+)
constexpr size_t F_SCC  = F_KVC  + 8 * Mi;   // [8,512,2048] x2
constexpr size_t F_SCR  = F_SCC  + 8 * Mi;
constexpr size_t F_SIMC = F_SCR  + 8 * Mi;
constexpr size_t F_SIMR = F_SIMC + Mi;
constexpr size_t F_BIAS = F_SIMR + Mi;
constexpr size_t F_TOTAL = F_BIAS + 4096;
__device__ float g_scratch[F_TOTAL];

// ------------------------- fp16 plane layout --------------------------------
constexpr size_t HXCH  = 0;                  // x hi [2048,1024] x2
constexpr size_t HWQH  = HXCH  + 4 * Mi;     // WqT hi [1024,1024] x2
constexpr size_t HWKH  = HWQH  + 2 * Mi;     // WkvT hi [2048,1024] x2
constexpr size_t HWLH  = HWKH  + 4 * Mi;     // WlinT hi [2048,2048] x2
constexpr size_t HK16  = HWLH  + 8 * Mi;     // raw k fp16 [2048,1024] x2
constexpr size_t HQ16  = HK16  + 4 * Mi;     // raw q fp16 [512,1024] x2
constexpr size_t HQH   = HQ16  + 1 * Mi;     // q norm hi [512,1024] x2
constexpr size_t HKH   = HQH   + 1 * Mi;     // k norm hi [2048,1024] x2
constexpr size_t HVNH  = HKH   + 4 * Mi;     // v norm hi [2048,1024] x2
constexpr size_t HVTH  = HVNH  + 4 * Mi;     // vT hi [1024,2048] x2
constexpr size_t HATH  = HVTH  + 4 * Mi;     // attn hi [8,512,2048]
constexpr size_t HS2H  = HATH  + 8 * Mi;     // s2 hi [512,2048]
constexpr size_t HOWH  = HS2H  + Mi;         // ow hi [512,2048]
constexpr size_t HXCCH = HOWH  + Mi;         // concat hi [512,2048] x2
constexpr size_t H_TOTAL = HXCCH + 2 * Mi;
__device__ __half g_half[H_TOTAL];

// ----------------------------- helpers --------------------------------------
__device__ __forceinline__ uint32_t smem_u32(const void* p) {
    uint32_t a;
    asm("{ .reg .u64 t; cvta.to.shared.u64 t, %1; cvt.u32.u64 %0, t; }"
        : "=r"(a) : "l"(p));
    return a;
}
__device__ __forceinline__ uint32_t pack2(__half a, __half b) {
    __half2 h = __halves2half2(a, b);
    return *(uint32_t*)&h;
}
__device__ __forceinline__ void ldsm4(uint32_t* r, uint32_t addr) {
    asm volatile("ldmatrix.sync.aligned.m8n8.x4.shared.b16 {%0,%1,%2,%3}, [%4];"
                 : "=r"(r[0]), "=r"(r[1]), "=r"(r[2]), "=r"(r[3]) : "r"(addr));
}
__device__ __forceinline__ void mma16816(float* d, const uint32_t* a, const uint32_t* b) {
    asm volatile("mma.sync.aligned.m16n8k16.row.col.f32.f16.f16.f32 "
                 "{%0,%1,%2,%3}, {%4,%5,%6,%7}, {%8,%9}, {%0,%1,%2,%3};"
                 : "+f"(d[0]), "+f"(d[1]), "+f"(d[2]), "+f"(d[3])
                 : "r"(a[0]), "r"(a[1]), "r"(a[2]), "r"(a[3]),
                   "r"(b[0]), "r"(b[1]));
}
__device__ __forceinline__ void cp16(uint32_t dst, const void* src) {
    asm volatile("cp.async.cg.shared.global [%0], [%1], 16;"
                 :: "r"(dst), "l"(src));
}
#define CP_COMMIT() asm volatile("cp.async.commit_group;" ::: "memory")
#define CP_WAIT1() asm volatile("cp.async.wait_group 1;" ::: "memory")
#define CP_WAIT0() asm volatile("cp.async.wait_group 0;" ::: "memory")

__device__ __forceinline__ uint32_t swz(int row, int chunk) {
    return (uint32_t)row * 64u + (uint32_t)((chunk ^ ((row >> 1) & 3)) << 4);
}

// ------------------------------- hgemm (NT) ----------------------------------
// C[M,N] = Ah[M,K] * Bh[N,K]^T. CTA 64x128x32, 4 warps (warp 32x64), occ 3.
template <bool BIAS, bool FOUT, bool SPLITOUT>
__global__ void __launch_bounds__(128, 3)
hgemm(const __half* __restrict__ Ah_g, const __half* __restrict__ Bh_g,
      const float* __restrict__ bias,
      float* C, __half* Chi,
      int K, int lda, int ldb, int ldc, int z1n,
      long long a_s1, long long a_s2, long long b_s1, long long b_s2,
      long long c_s1, long long c_s2, long long bias_s)
{
    constexpr int TM = 64, TN = 128;
    constexpr int ASZ = TM * 64;
    constexpr int BSZ = TN * 64;
    constexpr int STAGE = ASZ + BSZ;
    constexpr int MI = 2, NB = 4, NJ = 8;

    extern __shared__ char dsm[];
    const uint32_t sb = smem_u32(dsm);
    const int tid = threadIdx.x;

    const int z1 = blockIdx.z % z1n, z2 = blockIdx.z / z1n;
    const long long aoff = (long long)z1 * a_s1 + (long long)z2 * a_s2 +
                           (long long)blockIdx.y * TM * lda;
    const long long boff = (long long)z1 * b_s1 + (long long)z2 * b_s2 +
                           (long long)blockIdx.x * TN * ldb;
    const long long coff = (long long)z1 * c_s1 + (long long)z2 * c_s2;
    Ah_g += aoff;
    Bh_g += boff;
    if (FOUT) C += coff;
    if (SPLITOUT) Chi += coff;
    if (BIAS) bias += z1 * bias_s;

    const int lrow = tid >> 2;
    const int lc16 = tid & 3;

    const int lane = tid & 31, w = tid >> 5;
    const int wm = (w >> 1) * 32;
    const int wn = (w & 1) * 64;
    const int g = lane >> 3, r = lane & 7;
    const int a_r  = r + ((g & 1) << 3);
    const int a_kc = g >> 1;
    const int b_r  = r + ((g >> 1) << 3);
    const int b_kc = g & 1;

    float acc[MI][NJ][4];
#pragma unroll
    for (int i = 0; i < MI; i++)
#pragma unroll
        for (int j = 0; j < NJ; j++)
#pragma unroll
            for (int e = 0; e < 4; e++) acc[i][j][e] = 0.f;

    auto LOADA = [&](int k0, int s) {
        const uint32_t base = sb + (uint32_t)s * STAGE;
#pragma unroll
        for (int j = 0; j < TM / 32; j++) {
            int row = lrow + j * 32;
            uint32_t so = swz(row, lc16);
            cp16(base + so, Ah_g + (size_t)row * lda + k0 + lc16 * 8);
        }
#pragma unroll
        for (int j = 0; j < TN / 32; j++) {
            int row = lrow + j * 32;
            uint32_t so = swz(row, lc16);
            cp16(base + ASZ + so, Bh_g + (size_t)row * ldb + k0 + lc16 * 8);
        }
        CP_COMMIT();
    };

    auto COMPUTE = [&](int s) {
        const uint32_t base = sb + (uint32_t)s * STAGE;
        const uint32_t bA = base, bB = base + ASZ;
#pragma unroll
        for (int ks = 0; ks < 2; ks++) {
            const int kc = ks * 2;
            uint32_t ah[4 * MI], bh[4 * NB];
#pragma unroll
            for (int i = 0; i < MI; i++)
                ldsm4(&ah[4 * i], bA + swz(wm + i * 16 + a_r, kc + a_kc));
#pragma unroll
            for (int t = 0; t < NB; t++)
                ldsm4(&bh[4 * t], bB + swz(wn + t * 16 + b_r, kc + b_kc));
#pragma unroll
            for (int i = 0; i < MI; i++)
#pragma unroll
                for (int j = 0; j < NJ; j++)
                    mma16816(acc[i][j], &ah[4 * i], &bh[2 * j]);
        }
    };

    const int T = K >> 5;
    LOADA(0, 0);
    for (int t = 0; t < T; t++) {
        if (t + 1 < T) {
            LOADA((t + 1) << 5, (t + 1) & 1);
            CP_WAIT1();
        } else {
            CP_WAIT0();
        }
        __syncthreads();
        COMPUTE(t & 1);
        __syncthreads();
    }

    const int rbase = blockIdx.y * TM + wm;
    const int cbase = blockIdx.x * TN + wn;
#pragma unroll
    for (int i = 0; i < MI; i++) {
#pragma unroll
        for (int j = 0; j < NJ; j++) {
            int row0 = rbase + i * 16 + (lane >> 2);
            int col = cbase + j * 8 + ((lane & 3) << 1);
            float2 v0 = {acc[i][j][0], acc[i][j][1]};
            float2 v1 = {acc[i][j][2], acc[i][j][3]};
            if (BIAS) {
                float2 b2 = *(const float2*)(bias + col);
                v0.x += b2.x; v0.y += b2.y;
                v1.x += b2.x; v1.y += b2.y;
            }
            if (FOUT) {
                *(float2*)(C + (size_t)row0 * ldc + col) = v0;
                *(float2*)(C + (size_t)(row0 + 8) * ldc + col) = v1;
            }
            if (SPLITOUT) {
                *(uint32_t*)(Chi + (size_t)row0 * ldc + col) =
                    pack2(__float2half_rn(v0.x), __float2half_rn(v0.y));
                *(uint32_t*)(Chi + (size_t)(row0 + 8) * ldc + col) =
                    pack2(__float2half_rn(v1.x), __float2half_rn(v1.y));
            }
        }
    }
}

// ------------- transpose + convert to fp16 (hi), dual source -----------------
__global__ void __launch_bounds__(256)
transpose_convert2(const float* __restrict__ in0, const float* __restrict__ in1,
                   __half* __restrict__ hi, int ldin, int ldout, long long dst_bs)
{
    const float* in = blockIdx.z ? in1 : in0;
    hi += blockIdx.z * dst_bs;
    __shared__ float t[32][33];
    const int bx = blockIdx.x * 32, by = blockIdx.y * 32;
    const int x = threadIdx.x, y = threadIdx.y;
#pragma unroll
    for (int j = 0; j < 32; j += 8)
        t[y + j][x] = in[(size_t)(by + y + j) * ldin + bx + x];
    __syncthreads();
#pragma unroll
    for (int j = 0; j < 32; j += 8) {
        size_t o = (size_t)(bx + y + j) * ldout + by + x;
        hi[o] = __float2half_rn(t[x][y + j]);
    }
}

// ------------------ plain convert to fp16 (hi), dual source ------------------
__global__ void __launch_bounds__(256)
convert2_f16(const float* __restrict__ in0, const float* __restrict__ in1,
             __half* __restrict__ hi, int n4, long long dst_bs)
{
    const float* in = blockIdx.y ? in1 : in0;
    hi += blockIdx.y * dst_bs;
    int i = blockIdx.x * 256 + threadIdx.x;
    if (i >= n4) return;
    float4 v = ((const float4*)in)[i];
    uint2 h;
    h.x = pack2(__float2half_rn(v.x), __float2half_rn(v.y));
    h.y = pack2(__float2half_rn(v.z), __float2half_rn(v.w));
    ((uint2*)hi)[i] = h;
}

// ------------------ L2 normalize (per head), fp32 in -> fp16 -----------------
__global__ void __launch_bounds__(256)
l2norm_h(const float* __restrict__ src, __half* __restrict__ hi,
         int lds, int ldd, int nvec, long long src_bs, long long dst_bs)
{
    src += blockIdx.y * src_bs;
    hi += blockIdx.y * dst_bs;
    int vec = blockIdx.x * 8 + (threadIdx.x >> 5);
    int lane = threadIdx.x & 31;
    if (vec >= nvec) return;
    int row = vec >> 3, h = vec & 7;
    const float* s = src + (size_t)row * lds + h * 128 + lane * 4;
    float4 v = *(const float4*)s;
    float ss = v.x * v.x + v.y * v.y + v.z * v.z + v.w * v.w;
#pragma unroll
    for (int o = 16; o; o >>= 1) ss += __shfl_xor_sync(0xffffffffu, ss, o);
    float inv = 1.0f / sqrtf(ss);
    uint2 hh;
    hh.x = pack2(__float2half_rn(v.x * inv), __float2half_rn(v.y * inv));
    hh.y = pack2(__float2half_rn(v.z * inv), __float2half_rn(v.w * inv));
    *(uint2*)(hi + (size_t)row * ldd + h * 128 + lane * 4) = hh;
}

// ------------------ L2 normalize (per head), fp16 in -> fp16 -----------------
__global__ void __launch_bounds__(256)
l2norm_h16(const __half* __restrict__ src, __half* __restrict__ hi,
           int lds, int ldd, int nvec, long long src_bs, long long dst_bs)
{
    src += blockIdx.y * src_bs;
    hi += blockIdx.y * dst_bs;
    int vec = blockIdx.x * 8 + (threadIdx.x >> 5);
    int lane = threadIdx.x & 31;
    if (vec >= nvec) return;
    int row = vec >> 3, h = vec & 7;
    const __half* s = src + (size_t)row * lds + h * 128 + lane * 4;
    uint2 raw = *(const uint2*)s;
    float2 a = __half22float2(*(__half2*)&raw.x);
    float2 b = __half22float2(*(__half2*)&raw.y);
    float ss = a.x * a.x + a.y * a.y + b.x * b.x + b.y * b.y;
#pragma unroll
    for (int o = 16; o; o >>= 1) ss += __shfl_xor_sync(0xffffffffu, ss, o);
    float inv = 1.0f / sqrtf(ss);
    uint2 hh;
    hh.x = pack2(__float2half_rn(a.x * inv), __float2half_rn(a.y * inv));
    hh.y = pack2(__float2half_rn(b.x * inv), __float2half_rn(b.y * inv));
    *(uint2*)(hi + (size_t)row * ldd + h * 128 + lane * 4) = hh;
}

// ------------------------------ block reductions -----------------------------
static __device__ __forceinline__ float blockReduceMax(float v) {
    __shared__ float s[8];
#pragma unroll
    for (int o = 16; o; o >>= 1) v = fmaxf(v, __shfl_xor_sync(0xffffffffu, v, o));
    if ((threadIdx.x & 31) == 0) s[threadIdx.x >> 5] = v;
    __syncthreads();
    v = s[threadIdx.x & 7];
#pragma unroll
    for (int o = 4; o; o >>= 1) v = fmaxf(v, __shfl_xor_sync(0xffffffffu, v, o));
    __syncthreads();
    return v;
}
static __device__ __forceinline__ float blockReduceSum(float v) {
    __shared__ float s[8];
#pragma unroll
    for (int o = 16; o; o >>= 1) v += __shfl_xor_sync(0xffffffffu, v, o);
    if ((threadIdx.x & 31) == 0) s[threadIdx.x >> 5] = v;
    __syncthreads();
    v = s[threadIdx.x & 7];
#pragma unroll
    for (int o = 4; o; o >>= 1) v += __shfl_xor_sync(0xffffffffu, v, o);
    __syncthreads();
    return v;
}

// --------- softmax blend, one block per (q, head), write attn hi -------------
__global__ void __launch_bounds__(256)
softmax_combine2(const float* __restrict__ sc_cls, const float* __restrict__ sc_reg,
                 const float* __restrict__ cls_score, __half* __restrict__ attn_h)
{
    const int q = blockIdx.x, h = blockIdx.y;
    const int tid = threadIdx.x;
    const float* pc = sc_cls + ((size_t)h * 512 + q) * 2048;
    const float* pr = sc_reg + ((size_t)h * 512 + q) * 2048;
    float c[8], r[8];
    float mc = -1e30f, mr = -1e30f;
#pragma unroll
    for (int j = 0; j < 8; j++) {
        int k = j * 256 + tid;
        c[j] = pc[k] * 25.0f * cls_score[k];
        r[j] = pr[k] * 25.0f;
        mc = fmaxf(mc, c[j]);
        mr = fmaxf(mr, r[j]);
    }
    mc = blockReduceMax(mc);
    mr = blockReduceMax(mr);
    float sc = 0.f, sr = 0.f;
#pragma unroll
    for (int j = 0; j < 8; j++) {
        c[j] = expf(c[j] - mc);
        r[j] = expf(r[j] - mr);
        sc += c[j];
        sr += r[j];
    }
    sc = blockReduceSum(sc);
    sr = blockReduceSum(sr);
    float ic = 0.5f / sc, ir = 0.5f / sr;
    __half* pa = attn_h + ((size_t)h * 512 + q) * 2048;
#pragma unroll
    for (int j = 0; j < 8; j++)
        pa[j * 256 + tid] = __float2half_rn(c[j] * ic + r[j] * ir);
}

// ----- masked renormalized second-round weights; asum recomputed from attn ---
__global__ void __launch_bounds__(256)
mask_renorm(const __half* __restrict__ attn_h, const float* __restrict__ simc,
            const float* __restrict__ simr,
            __half* __restrict__ s2h, __half* __restrict__ owh)
{
    const int q = blockIdx.x;
    const int tid = threadIdx.x;
    float a[8];
    float mx = -1e30f;
#pragma unroll
    for (int j = 0; j < 8; j++) {
        int k = j * 256 + tid;
        float s = 0.f;
#pragma unroll
        for (int h = 0; h < 8; h++)
            s += __half2float(attn_h[((size_t)h * 512 + q) * 2048 + k]);
        a[j] = s * 0.125f;
        mx = fmaxf(mx, a[j]);
    }
    mx = blockReduceMax(mx);
    float sum = 0.f;
#pragma unroll
    for (int j = 0; j < 8; j++) {
        a[j] = expf(a[j] - mx);
        sum += a[j];
    }
    sum = blockReduceSum(sum);
    float inv = 1.0f / sum;
    float sm = 0.f;
#pragma unroll
    for (int j = 0; j < 8; j++) {
        int k = j * 256 + tid;
        float m = (simc[(size_t)q * 2048 + k] * 0.125f > 0.75f) ? 1.0f : 0.0f;
        a[j] = a[j] * inv * m;
        sm += a[j];
    }
    sm = blockReduceSum(sm);
    inv = 1.0f / sm;
    float so = 0.f;
    float o[8];
#pragma unroll
    for (int j = 0; j < 8; j++) {
        int k = j * 256 + tid;
        a[j] *= inv;
        s2h[(size_t)q * 2048 + k] = __float2half_rn(a[j]);
        float m = (simr[(size_t)q * 2048 + k] * 0.125f > 0.99f) ? 1.0f : 0.0f;
        o[j] = a[j] * m;
        so += o[j];
    }
    so = blockReduceSum(so);
    inv = 1.0f / so;
#pragma unroll
    for (int j = 0; j < 8; j++)
        owh[(size_t)q * 2048 + j * 256 + tid] = __float2half_rn(o[j] * inv);
}

// -------------------- copy x_ori into concat (hi only) -----------------------
__global__ void __launch_bounds__(256)
copy_xori(const float* __restrict__ kv, __half* __restrict__ xh)
{
    int z = blockIdx.y;
    kv += (size_t)z * 4 * Mi;
    xh += (size_t)z * Mi;
    int idx = blockIdx.x * 256 + threadIdx.x;
    int q = idx >> 8;
    int c4 = idx & 255;
    size_t off = (size_t)q * 2048 + 1024 + (size_t)c4 * 4;
    float4 v = *(const float4*)(kv + off);
    *(uint32_t*)(xh + off) = pack2(__float2half_rn(v.x), __float2half_rn(v.y));
    *(uint32_t*)(xh + off + 2) = pack2(__float2half_rn(v.z), __float2half_rn(v.w));
}

// ------------------------------ bias copy ------------------------------------
__global__ void copy_bias(const float* __restrict__ b0, const float* __restrict__ b1,
                          float* __restrict__ dst)
{
    int i = blockIdx.x * 256 + threadIdx.x;
    if (i < 2048) { dst[i] = b0[i]; dst[2048 + i] = b1[i]; }
}

// --------------------------------- launch ------------------------------------
extern "C" void kernel_launch(void* const* d_in, const int* in_sizes, int n_in,
                              void* d_out, int out_size)
{
    const float* x_cls     = (const float*)d_in[0];
    const float* x_reg     = (const float*)d_in[1];
    const float* cls_score = (const float*)d_in[2];
    const float* W_q_cls   = (const float*)d_in[4];
    const float* W_kv_cls  = (const float*)d_in[5];
    const float* W_q_reg   = (const float*)d_in[6];
    const float* W_kv_reg  = (const float*)d_in[7];
    const float* W_lin     = (const float*)d_in[8];
    const float* b_lin     = (const float*)d_in[9];
    const float* W_lin_reg = (const float*)d_in[10];
    const float* b_lin_reg = (const float*)d_in[11];
    float* out = (float*)d_out;

    float* F = nullptr;
    __half* Hp = nullptr;
    cudaGetSymbolAddress((void**)&F, g_scratch);
    cudaGetSymbolAddress((void**)&Hp, g_half);

    float* kvc  = F + F_KVC;
    float* scc  = F + F_SCC;
    float* scr  = F + F_SCR;
    float* simc = F + F_SIMC;
    float* simr = F + F_SIMR;
    float* bias2 = F + F_BIAS;

    constexpr int SM64 = 2 * (4096 + 8192);  // 24576

    auto gf  = hgemm<false, true, false>;    // fp32 out
    auto gs  = hgemm<false, false, true>;    // fp16 out
    auto gb  = hgemm<true, true, false>;     // fp32 out + bias
    cudaFuncSetAttribute(gf, cudaFuncAttributeMaxDynamicSharedMemorySize, SM64);
    cudaFuncSetAttribute(gs, cudaFuncAttributeMaxDynamicSharedMemorySize, SM64);
    cudaFuncSetAttribute(gb, cudaFuncAttributeMaxDynamicSharedMemorySize, SM64);

    static bool s_init = false;
    static cudaStream_t sB;
    static cudaEvent_t eFork, eX, eQ, eVT, eXori, eSoft, eEnd;
    if (!s_init) {
        cudaStreamCreateWithFlags(&sB, cudaStreamNonBlocking);
        cudaEventCreateWithFlags(&eFork, cudaEventDisableTiming);
        cudaEventCreateWithFlags(&eX, cudaEventDisableTiming);
        cudaEventCreateWithFlags(&eQ, cudaEventDisableTiming);
        cudaEventCreateWithFlags(&eVT, cudaEventDisableTiming);
        cudaEventCreateWithFlags(&eXori, cudaEventDisableTiming);
        cudaEventCreateWithFlags(&eSoft, cudaEventDisableTiming);
        cudaEventCreateWithFlags(&eEnd, cudaEventDisableTiming);
        s_init = true;
    }
    cudaStream_t sA = 0;

    dim3 tb(32, 8);
    const long long OSTR = 512LL * 3072;

    // ===== fork =====
    cudaEventRecord(eFork, sA);
    cudaStreamWaitEvent(sB, eFork, 0);

    // --- sA: x converts + Wkv transpose ---
    convert2_f16<<<dim3(2048, 2), 256, 0, sA>>>(x_cls, x_reg, Hp + HXCH,
                                                2048 * 256, 2 * Mi);
    transpose_convert2<<<dim3(64, 32, 2), tb, 0, sA>>>(W_kv_cls, W_kv_reg,
                                                       Hp + HWKH, 2048, 1024, 2 * Mi);
    cudaEventRecord(eX, sA);

    // --- sA: k projection (fp16 out) -> l2norm k (fp16 in) ---
    gs<<<dim3(8, 32, 2), 128, SM64, sA>>>(
        Hp + HXCH, Hp + HWKH, nullptr,
        nullptr, Hp + HK16, 1024, 1024, 1024, 1024,
        2, 2 * Mi, 0, 2 * Mi, 0, 2 * Mi, 0, 0);
    l2norm_h16<<<dim3(2048, 2), 256, 0, sA>>>(Hp + HK16, Hp + HKH,
                                              1024, 1024, 2048 * 8, 2 * Mi, 2 * Mi);

    // --- sB: Wq/Wlin transposes + bias -> q projection (fp16) + l2norm q ---
    transpose_convert2<<<dim3(32, 32, 2), tb, 0, sB>>>(W_q_cls, W_q_reg,
                                                       Hp + HWQH, 1024, 1024, Mi);
    transpose_convert2<<<dim3(64, 64, 2), tb, 0, sB>>>(W_lin, W_lin_reg,
                                                       Hp + HWLH, 2048, 2048, 4 * Mi);
    copy_bias<<<8, 256, 0, sB>>>(b_lin, b_lin_reg, bias2);
    cudaStreamWaitEvent(sB, eX, 0);
    gs<<<dim3(8, 8, 2), 128, SM64, sB>>>(
        Hp + HXCH, Hp + HWQH, nullptr,
        nullptr, Hp + HQ16, 1024, 1024, 1024, 1024,
        2, 2 * Mi, 0, Mi, 0, Mi / 2, 0, 0);
    l2norm_h16<<<dim3(512, 2), 256, 0, sB>>>(Hp + HQ16, Hp + HQH,
                                             1024, 1024, 512 * 8, Mi / 2, Mi / 2);
    cudaEventRecord(eQ, sB);

    // --- sB: v projection (fp32 out) + v norm + vT + xori + sims ---
    gf<<<dim3(8, 32, 2), 128, SM64, sB>>>(
        Hp + HXCH, Hp + HWKH + Mi, nullptr,
        kvc + 1024, nullptr, 1024, 1024, 1024, 2048,
        2, 2 * Mi, 0, 2 * Mi, 0, 4 * Mi, 0, 0);
    l2norm_h<<<dim3(2048, 2), 256, 0, sB>>>(kvc + 1024, Hp + HVNH,
                                            2048, 1024, 2048 * 8, 4 * Mi, 2 * Mi);
    transpose_convert2<<<dim3(32, 64, 2), tb, 0, sB>>>(kvc + 1024, kvc + 4 * Mi + 1024,
                                                       Hp + HVTH, 2048, 2048, 2 * Mi);
    cudaEventRecord(eVT, sB);
    copy_xori<<<dim3(512, 2), 256, 0, sB>>>(kvc, Hp + HXCCH);
    cudaEventRecord(eXori, sB);
    gf<<<dim3(16, 8, 2), 128, SM64, sB>>>(
        Hp + HVNH, Hp + HVNH, nullptr,
        simc, nullptr, 1024, 1024, 1024, 2048,
        2, 2 * Mi, 0, 2 * Mi, 0, Mi, 0, 0);

    // --- sA: scores (needs q) -> softmax ---
    cudaStreamWaitEvent(sA, eQ, 0);
    gf<<<dim3(16, 8, 16), 128, SM64, sA>>>(
        Hp + HQH, Hp + HKH, nullptr,
        scc, nullptr, 128, 1024, 1024, 2048,
        8, 128, Mi / 2, 128, 2 * Mi, Mi, 8 * Mi, 0);
    softmax_combine2<<<dim3(512, 8), 256, 0, sA>>>(scc, scr, cls_score, Hp + HATH);
    cudaEventRecord(eSoft, sA);

    // --- sA: attn@v (needs vT) -> out-linears (needs xori) ---
    cudaStreamWaitEvent(sA, eVT, 0);
    gs<<<dim3(1, 8, 16), 128, SM64, sA>>>(
        Hp + HATH, Hp + HVTH, nullptr,
        nullptr, Hp + HXCCH, 2048, 2048, 2048, 2048,
        8, Mi, 0, 128LL * 2048, 2 * Mi, 128, Mi, 0);
    cudaStreamWaitEvent(sA, eXori, 0);
    gb<<<dim3(16, 8, 2), 128, SM64, sA>>>(
        Hp + HXCCH, Hp + HWLH, bias2,
        out + 1024, nullptr, 2048, 2048, 2048, 3072,
        2, Mi, 0, 4 * Mi, 0, OSTR, 0, 2048);

    // --- sB: mask_renorm (needs attn + sims) -> support ---
    cudaStreamWaitEvent(sB, eSoft, 0);
    mask_renorm<<<512, 256, 0, sB>>>(Hp + HATH, simc, simr, Hp + HS2H, Hp + HOWH);
    gf<<<dim3(8, 8, 2), 128, SM64, sB>>>(
        Hp + HS2H, Hp + HVTH, nullptr,
        out, nullptr, 2048, 2048, 2048, 3072,
        2, Mi, 0, 2 * Mi, 0, OSTR, 0, 0);
    cudaEventRecord(eEnd, sB);

    // ===== join =====
    cudaStreamWaitEvent(sA, eEnd, 0);
}

// round 16
// speedup vs baseline: 1.1506x; 1.0318x over previous
#include <cuda_runtime.h>
#include <cuda_fp16.h>
#include <cstdint>

// ===========================================================================
// Fixed shapes: B=1, N1=512, N2=2048, C=1024, H=8, hd=128
// All GEMMs: mma.sync m16n8k16 fp16, fp32 acc, 1-term. TM=64 tiles.
// fp16 intermediates everywhere; xori fused into v-proj epilogue;
// sims GEMM emits uint8 threshold masks directly.
// ===========================================================================

constexpr size_t Mi = 1024 * 1024;

// ------------------------- fp32 scratch layout ------------------------------
constexpr size_t F_SCC  = 0;                 // [8,512,2048] x2
constexpr size_t F_SCR  = F_SCC + 8 * Mi;
constexpr size_t F_BIAS = F_SCR + 8 * Mi;    // [2,2048]
constexpr size_t F_TOTAL = F_BIAS + 4096;
__device__ float g_scratch[F_TOTAL];

__device__ uint8_t g_mask[2 * Mi];           // simc/simr masks [512,2048] x2

// ------------------------- fp16 plane layout --------------------------------
constexpr size_t HXCH  = 0;                  // x hi [2048,1024] x2
constexpr size_t HWQH  = HXCH  + 4 * Mi;     // WqT hi [1024,1024] x2
constexpr size_t HWKH  = HWQH  + 2 * Mi;     // WkvT hi [2048,1024] x2
constexpr size_t HWLH  = HWKH  + 4 * Mi;     // WlinT hi [2048,2048] x2
constexpr size_t HK16  = HWLH  + 8 * Mi;     // raw k fp16 [2048,1024] x2
constexpr size_t HQ16  = HK16  + 4 * Mi;     // raw q fp16 [512,1024] x2
constexpr size_t HV16  = HQ16  + 1 * Mi;     // raw v fp16 [2048,1024] x2
constexpr size_t HQH   = HV16  + 4 * Mi;     // q norm hi [512,1024] x2
constexpr size_t HKH   = HQH   + 1 * Mi;     // k norm hi [2048,1024] x2
constexpr size_t HVNH  = HKH   + 4 * Mi;     // v norm hi [2048,1024] x2
constexpr size_t HVTH  = HVNH  + 4 * Mi;     // vT hi [1024,2048] x2
constexpr size_t HATH  = HVTH  + 4 * Mi;     // attn hi [8,512,2048]
constexpr size_t HS2H  = HATH  + 8 * Mi;     // s2 hi [512,2048]
constexpr size_t HOWH  = HS2H  + Mi;         // ow hi [512,2048]
constexpr size_t HXCCH = HOWH  + Mi;         // concat hi [512,2048] x2
constexpr size_t H_TOTAL = HXCCH + 2 * Mi;
__device__ __half g_half[H_TOTAL];

// ----------------------------- helpers --------------------------------------
__device__ __forceinline__ uint32_t smem_u32(const void* p) {
    uint32_t a;
    asm("{ .reg .u64 t; cvta.to.shared.u64 t, %1; cvt.u32.u64 %0, t; }"
        : "=r"(a) : "l"(p));
    return a;
}
__device__ __forceinline__ uint32_t pack2(__half a, __half b) {
    __half2 h = __halves2half2(a, b);
    return *(uint32_t*)&h;
}
__device__ __forceinline__ void ldsm4(uint32_t* r, uint32_t addr) {
    asm volatile("ldmatrix.sync.aligned.m8n8.x4.shared.b16 {%0,%1,%2,%3}, [%4];"
                 : "=r"(r[0]), "=r"(r[1]), "=r"(r[2]), "=r"(r[3]) : "r"(addr));
}
__device__ __forceinline__ void mma16816(float* d, const uint32_t* a, const uint32_t* b) {
    asm volatile("mma.sync.aligned.m16n8k16.row.col.f32.f16.f16.f32 "
                 "{%0,%1,%2,%3}, {%4,%5,%6,%7}, {%8,%9}, {%0,%1,%2,%3};"
                 : "+f"(d[0]), "+f"(d[1]), "+f"(d[2]), "+f"(d[3])
                 : "r"(a[0]), "r"(a[1]), "r"(a[2]), "r"(a[3]),
                   "r"(b[0]), "r"(b[1]));
}
__device__ __forceinline__ void cp16(uint32_t dst, const void* src) {
    asm volatile("cp.async.cg.shared.global [%0], [%1], 16;"
                 :: "r"(dst), "l"(src));
}
#define CP_COMMIT() asm volatile("cp.async.commit_group;" ::: "memory")
#define CP_WAIT1() asm volatile("cp.async.wait_group 1;" ::: "memory")
#define CP_WAIT0() asm volatile("cp.async.wait_group 0;" ::: "memory")

__device__ __forceinline__ uint32_t swz(int row, int chunk) {
    return (uint32_t)row * 64u + (uint32_t)((chunk ^ ((row >> 1) & 3)) << 4);
}

// ------------------------------- hgemm (NT) ----------------------------------
// C[M,N] = Ah[M,K] * Bh[N,K]^T. CTA 64x128x32, 4 warps (warp 32x64), occ 3.
// MODE: 0 = fp32 out; 1 = fp32 out + bias; 2 = fp16 out;
//       3 = fp16 out + xori mirror (rows<512 -> Cx[row*2048+1024+col]);
//       4 = uint8 mask out (val*0.125 > thresh[z1])
template <int MODE>
__global__ void __launch_bounds__(128, 3)
hgemm(const __half* __restrict__ Ah_g, const __half* __restrict__ Bh_g,
      const float* __restrict__ bias,
      float* C, __half* Chi, __half* Cx, uint8_t* Cm,
      float th0, float th1,
      int K, int lda, int ldb, int ldc, int z1n,
      long long a_s1, long long a_s2, long long b_s1, long long b_s2,
      long long c_s1, long long c_s2, long long bias_s, long long x_s1)
{
    constexpr int TM = 64, TN = 128;
    constexpr int ASZ = TM * 64;
    constexpr int BSZ = TN * 64;
    constexpr int STAGE = ASZ + BSZ;
    constexpr int MI = 2, NB = 4, NJ = 8;

    extern __shared__ char dsm[];
    const uint32_t sb = smem_u32(dsm);
    const int tid = threadIdx.x;

    const int z1 = blockIdx.z % z1n, z2 = blockIdx.z / z1n;
    const long long aoff = (long long)z1 * a_s1 + (long long)z2 * a_s2 +
                           (long long)blockIdx.y * TM * lda;
    const long long boff = (long long)z1 * b_s1 + (long long)z2 * b_s2 +
                           (long long)blockIdx.x * TN * ldb;
    const long long coff = (long long)z1 * c_s1 + (long long)z2 * c_s2;
    Ah_g += aoff;
    Bh_g += boff;
    if (MODE <= 1) C += coff;
    if (MODE == 2 || MODE == 3) Chi += coff;
    if (MODE == 3) Cx += (long long)z1 * x_s1;
    if (MODE == 4) Cm += coff;
    if (MODE == 1) bias += z1 * bias_s;
    const float thr = (MODE == 4) ? (z1 ? th1 : th0) : 0.f;

    const int lrow = tid >> 2;
    const int lc16 = tid & 3;

    const int lane = tid & 31, w = tid >> 5;
    const int wm = (w >> 1) * 32;
    const int wn = (w & 1) * 64;
    const int g = lane >> 3, r = lane & 7;
    const int a_r  = r + ((g & 1) << 3);
    const int a_kc = g >> 1;
    const int b_r  = r + ((g >> 1) << 3);
    const int b_kc = g & 1;

    float acc[MI][NJ][4];
#pragma unroll
    for (int i = 0; i < MI; i++)
#pragma unroll
        for (int j = 0; j < NJ; j++)
#pragma unroll
            for (int e = 0; e < 4; e++) acc[i][j][e] = 0.f;

    auto LOADA = [&](int k0, int s) {
        const uint32_t base = sb + (uint32_t)s * STAGE;
#pragma unroll
        for (int j = 0; j < TM / 32; j++) {
            int row = lrow + j * 32;
            uint32_t so = swz(row, lc16);
            cp16(base + so, Ah_g + (size_t)row * lda + k0 + lc16 * 8);
        }
#pragma unroll
        for (int j = 0; j < TN / 32; j++) {
            int row = lrow + j * 32;
            uint32_t so = swz(row, lc16);
            cp16(base + ASZ + so, Bh_g + (size_t)row * ldb + k0 + lc16 * 8);
        }
        CP_COMMIT();
    };

    auto COMPUTE = [&](int s) {
        const uint32_t base = sb + (uint32_t)s * STAGE;
        const uint32_t bA = base, bB = base + ASZ;
#pragma unroll
        for (int ks = 0; ks < 2; ks++) {
            const int kc = ks * 2;
            uint32_t ah[4 * MI], bh[4 * NB];
#pragma unroll
            for (int i = 0; i < MI; i++)
                ldsm4(&ah[4 * i], bA + swz(wm + i * 16 + a_r, kc + a_kc));
#pragma unroll
            for (int t = 0; t < NB; t++)
                ldsm4(&bh[4 * t], bB + swz(wn + t * 16 + b_r, kc + b_kc));
#pragma unroll
            for (int i = 0; i < MI; i++)
#pragma unroll
                for (int j = 0; j < NJ; j++)
                    mma16816(acc[i][j], &ah[4 * i], &bh[2 * j]);
        }
    };

    const int T = K >> 5;
    LOADA(0, 0);
    for (int t = 0; t < T; t++) {
        if (t + 1 < T) {
            LOADA((t + 1) << 5, (t + 1) & 1);
            CP_WAIT1();
        } else {
            CP_WAIT0();
        }
        __syncthreads();
        COMPUTE(t & 1);
        __syncthreads();
    }

    const int rbase = blockIdx.y * TM + wm;
    const int cbase = blockIdx.x * TN + wn;
#pragma unroll
    for (int i = 0; i < MI; i++) {
#pragma unroll
        for (int j = 0; j < NJ; j++) {
            int row0 = rbase + i * 16 + (lane >> 2);
            int col = cbase + j * 8 + ((lane & 3) << 1);
            float2 v0 = {acc[i][j][0], acc[i][j][1]};
            float2 v1 = {acc[i][j][2], acc[i][j][3]};
            if (MODE == 1) {
                float2 b2 = *(const float2*)(bias + col);
                v0.x += b2.x; v0.y += b2.y;
                v1.x += b2.x; v1.y += b2.y;
            }
            if (MODE <= 1) {
                *(float2*)(C + (size_t)row0 * ldc + col) = v0;
                *(float2*)(C + (size_t)(row0 + 8) * ldc + col) = v1;
            }
            if (MODE == 2 || MODE == 3) {
                uint32_t p0 = pack2(__float2half_rn(v0.x), __float2half_rn(v0.y));
                uint32_t p1 = pack2(__float2half_rn(v1.x), __float2half_rn(v1.y));
                *(uint32_t*)(Chi + (size_t)row0 * ldc + col) = p0;
                *(uint32_t*)(Chi + (size_t)(row0 + 8) * ldc + col) = p1;
                if (MODE == 3) {
                    if (row0 < 512)
                        *(uint32_t*)(Cx + (size_t)row0 * 2048 + 1024 + col) = p0;
                    if (row0 + 8 < 512)
                        *(uint32_t*)(Cx + (size_t)(row0 + 8) * 2048 + 1024 + col) = p1;
                }
            }
            if (MODE == 4) {
                uchar2 m0 = {(uint8_t)(v0.x * 0.125f > thr),
                             (uint8_t)(v0.y * 0.125f > thr)};
                uchar2 m1 = {(uint8_t)(v1.x * 0.125f > thr),
                             (uint8_t)(v1.y * 0.125f > thr)};
                *(uchar2*)(Cm + (size_t)row0 * ldc + col) = m0;
                *(uchar2*)(Cm + (size_t)(row0 + 8) * ldc + col) = m1;
            }
        }
    }
}

// ------------- transpose + convert to fp16 (hi), dual source (fp32 in) -------
__global__ void __launch_bounds__(256)
transpose_convert2(const float* __restrict__ in0, const float* __restrict__ in1,
                   __half* __restrict__ hi, int ldin, int ldout, long long dst_bs)
{
    const float* in = blockIdx.z ? in1 : in0;
    hi += blockIdx.z * dst_bs;
    __shared__ float t[32][33];
    const int bx = blockIdx.x * 32, by = blockIdx.y * 32;
    const int x = threadIdx.x, y = threadIdx.y;
#pragma unroll
    for (int j = 0; j < 32; j += 8)
        t[y + j][x] = in[(size_t)(by + y + j) * ldin + bx + x];
    __syncthreads();
#pragma unroll
    for (int j = 0; j < 32; j += 8) {
        size_t o = (size_t)(bx + y + j) * ldout + by + x;
        hi[o] = __float2half_rn(t[x][y + j]);
    }
}

// --------------------- fp16 -> fp16 transpose, branch batched ----------------
__global__ void __launch_bounds__(256)
transpose16(const __half* __restrict__ in, __half* __restrict__ outp,
            int ldin, int ldout, long long src_bs, long long dst_bs)
{
    in += blockIdx.z * src_bs;
    outp += blockIdx.z * dst_bs;
    __shared__ __half t[32][34];
    const int bx = blockIdx.x * 32, by = blockIdx.y * 32;
    const int x = threadIdx.x, y = threadIdx.y;
#pragma unroll
    for (int j = 0; j < 32; j += 8)
        t[y + j][x] = in[(size_t)(by + y + j) * ldin + bx + x];
    __syncthreads();
#pragma unroll
    for (int j = 0; j < 32; j += 8)
        outp[(size_t)(bx + y + j) * ldout + by + x] = t[x][y + j];
}

// ------------------ plain convert to fp16 (hi), dual source ------------------
__global__ void __launch_bounds__(256)
convert2_f16(const float* __restrict__ in0, const float* __restrict__ in1,
             __half* __restrict__ hi, int n4, long long dst_bs)
{
    const float* in = blockIdx.y ? in1 : in0;
    hi += blockIdx.y * dst_bs;
    int i = blockIdx.x * 256 + threadIdx.x;
    if (i >= n4) return;
    float4 v = ((const float4*)in)[i];
    uint2 h;
    h.x = pack2(__float2half_rn(v.x), __float2half_rn(v.y));
    h.y = pack2(__float2half_rn(v.z), __float2half_rn(v.w));
    ((uint2*)hi)[i] = h;
}

// ------------------ L2 normalize (per head), fp16 in -> fp16 -----------------
__global__ void __launch_bounds__(256)
l2norm_h16(const __half* __restrict__ src, __half* __restrict__ hi,
           int lds, int ldd, int nvec, long long src_bs, long long dst_bs)
{
    src += blockIdx.y * src_bs;
    hi += blockIdx.y * dst_bs;
    int vec = blockIdx.x * 8 + (threadIdx.x >> 5);
    int lane = threadIdx.x & 31;
    if (vec >= nvec) return;
    int row = vec >> 3, h = vec & 7;
    const __half* s = src + (size_t)row * lds + h * 128 + lane * 4;
    uint2 raw = *(const uint2*)s;
    float2 a = __half22float2(*(__half2*)&raw.x);
    float2 b = __half22float2(*(__half2*)&raw.y);
    float ss = a.x * a.x + a.y * a.y + b.x * b.x + b.y * b.y;
#pragma unroll
    for (int o = 16; o; o >>= 1) ss += __shfl_xor_sync(0xffffffffu, ss, o);
    float inv = 1.0f / sqrtf(ss);
    uint2 hh;
    hh.x = pack2(__float2half_rn(a.x * inv), __float2half_rn(a.y * inv));
    hh.y = pack2(__float2half_rn(b.x * inv), __float2half_rn(b.y * inv));
    *(uint2*)(hi + (size_t)row * ldd + h * 128 + lane * 4) = hh;
}

// ------------------------------ block reductions -----------------------------
static __device__ __forceinline__ float blockReduceMax(float v) {
    __shared__ float s[8];
#pragma unroll
    for (int o = 16; o; o >>= 1) v = fmaxf(v, __shfl_xor_sync(0xffffffffu, v, o));
    if ((threadIdx.x & 31) == 0) s[threadIdx.x >> 5] = v;
    __syncthreads();
    v = s[threadIdx.x & 7];
#pragma unroll
    for (int o = 4; o; o >>= 1) v = fmaxf(v, __shfl_xor_sync(0xffffffffu, v, o));
    __syncthreads();
    return v;
}
static __device__ __forceinline__ float blockReduceSum(float v) {
    __shared__ float s[8];
#pragma unroll
    for (int o = 16; o; o >>= 1) v += __shfl_xor_sync(0xffffffffu, v, o);
    if ((threadIdx.x & 31) == 0) s[threadIdx.x >> 5] = v;
    __syncthreads();
    v = s[threadIdx.x & 7];
#pragma unroll
    for (int o = 4; o; o >>= 1) v += __shfl_xor_sync(0xffffffffu, v, o);
    __syncthreads();
    return v;
}

// --------- softmax blend, one block per (q, head), write attn hi -------------
__global__ void __launch_bounds__(256)
softmax_combine2(const float* __restrict__ sc_cls, const float* __restrict__ sc_reg,
                 const float* __restrict__ cls_score, __half* __restrict__ attn_h)
{
    const int q = blockIdx.x, h = blockIdx.y;
    const int tid = threadIdx.x;
    const float* pc = sc_cls + ((size_t)h * 512 + q) * 2048;
    const float* pr = sc_reg + ((size_t)h * 512 + q) * 2048;
    float c[8], r[8];
    float mc = -1e30f, mr = -1e30f;
#pragma unroll
    for (int j = 0; j < 8; j++) {
        int k = j * 256 + tid;
        c[j] = pc[k] * 25.0f * cls_score[k];
        r[j] = pr[k] * 25.0f;
        mc = fmaxf(mc, c[j]);
        mr = fmaxf(mr, r[j]);
    }
    mc = blockReduceMax(mc);
    mr = blockReduceMax(mr);
    float sc = 0.f, sr = 0.f;
#pragma unroll
    for (int j = 0; j < 8; j++) {
        c[j] = expf(c[j] - mc);
        r[j] = expf(r[j] - mr);
        sc += c[j];
        sr += r[j];
    }
    sc = blockReduceSum(sc);
    sr = blockReduceSum(sr);
    float ic = 0.5f / sc, ir = 0.5f / sr;
    __half* pa = attn_h + ((size_t)h * 512 + q) * 2048;
#pragma unroll
    for (int j = 0; j < 8; j++)
        pa[j * 256 + tid] = __float2half_rn(c[j] * ic + r[j] * ir);
}

// ----- masked renormalized second-round weights; asum from attn, u8 masks ----
__global__ void __launch_bounds__(256)
mask_renorm(const __half* __restrict__ attn_h, const uint8_t* __restrict__ maskc,
            const uint8_t* __restrict__ maskr,
            __half* __restrict__ s2h, __half* __restrict__ owh)
{
    const int q = blockIdx.x;
    const int tid = threadIdx.x;
    float a[8];
    float mx = -1e30f;
#pragma unroll
    for (int j = 0; j < 8; j++) {
        int k = j * 256 + tid;
        float s = 0.f;
#pragma unroll
        for (int h = 0; h < 8; h++)
            s += __half2float(attn_h[((size_t)h * 512 + q) * 2048 + k]);
        a[j] = s * 0.125f;
        mx = fmaxf(mx, a[j]);
    }
    mx = blockReduceMax(mx);
    float sum = 0.f;
#pragma unroll
    for (int j = 0; j < 8; j++) {
        a[j] = expf(a[j] - mx);
        sum += a[j];
    }
    sum = blockReduceSum(sum);
    float inv = 1.0f / sum;
    float sm = 0.f;
#pragma unroll
    for (int j = 0; j < 8; j++) {
        int k = j * 256 + tid;
        a[j] = maskc[(size_t)q * 2048 + k] ? a[j] * inv : 0.f;
        sm += a[j];
    }
    sm = blockReduceSum(sm);
    inv = 1.0f / sm;
    float so = 0.f;
    float o[8];
#pragma unroll
    for (int j = 0; j < 8; j++) {
        int k = j * 256 + tid;
        a[j] *= inv;
        s2h[(size_t)q * 2048 + k] = __float2half_rn(a[j]);
        o[j] = maskr[(size_t)q * 2048 + k] ? a[j] : 0.f;
        so += o[j];
    }
    so = blockReduceSum(so);
    inv = 1.0f / so;
#pragma unroll
    for (int j = 0; j < 8; j++)
        owh[(size_t)q * 2048 + j * 256 + tid] = __float2half_rn(o[j] * inv);
}

// ------------------------------ bias copy ------------------------------------
__global__ void copy_bias(const float* __restrict__ b0, const float* __restrict__ b1,
                          float* __restrict__ dst)
{
    int i = blockIdx.x * 256 + threadIdx.x;
    if (i < 2048) { dst[i] = b0[i]; dst[2048 + i] = b1[i]; }
}

// --------------------------------- launch ------------------------------------
extern "C" void kernel_launch(void* const* d_in, const int* in_sizes, int n_in,
                              void* d_out, int out_size)
{
    const float* x_cls     = (const float*)d_in[0];
    const float* x_reg     = (const float*)d_in[1];
    const float* cls_score = (const float*)d_in[2];
    const float* W_q_cls   = (const float*)d_in[4];
    const float* W_kv_cls  = (const float*)d_in[5];
    const float* W_q_reg   = (const float*)d_in[6];
    const float* W_kv_reg  = (const float*)d_in[7];
    const float* W_lin     = (const float*)d_in[8];
    const float* b_lin     = (const float*)d_in[9];
    const float* W_lin_reg = (const float*)d_in[10];
    const float* b_lin_reg = (const float*)d_in[11];
    float* out = (float*)d_out;

    float* F = nullptr;
    __half* Hp = nullptr;
    uint8_t* Mp = nullptr;
    cudaGetSymbolAddress((void**)&F, g_scratch);
    cudaGetSymbolAddress((void**)&Hp, g_half);
    cudaGetSymbolAddress((void**)&Mp, g_mask);

    float* scc  = F + F_SCC;
    float* scr  = F + F_SCR;
    float* bias2 = F + F_BIAS;

    constexpr int SM64 = 2 * (4096 + 8192);  // 24576

    auto g0 = hgemm<0>;  // fp32 out
    auto g1 = hgemm<1>;  // fp32 out + bias
    auto g2 = hgemm<2>;  // fp16 out
    auto g3 = hgemm<3>;  // fp16 out + xori mirror
    auto g4 = hgemm<4>;  // u8 mask out
    cudaFuncSetAttribute(g0, cudaFuncAttributeMaxDynamicSharedMemorySize, SM64);
    cudaFuncSetAttribute(g1, cudaFuncAttributeMaxDynamicSharedMemorySize, SM64);
    cudaFuncSetAttribute(g2, cudaFuncAttributeMaxDynamicSharedMemorySize, SM64);
    cudaFuncSetAttribute(g3, cudaFuncAttributeMaxDynamicSharedMemorySize, SM64);
    cudaFuncSetAttribute(g4, cudaFuncAttributeMaxDynamicSharedMemorySize, SM64);

    static bool s_init = false;
    static cudaStream_t sB;
    static cudaEvent_t eFork, eX, eQ, eVT, eXori, eSoft, eEnd;
    if (!s_init) {
        cudaStreamCreateWithFlags(&sB, cudaStreamNonBlocking);
        cudaEventCreateWithFlags(&eFork, cudaEventDisableTiming);
        cudaEventCreateWithFlags(&eX, cudaEventDisableTiming);
        cudaEventCreateWithFlags(&eQ, cudaEventDisableTiming);
        cudaEventCreateWithFlags(&eVT, cudaEventDisableTiming);
        cudaEventCreateWithFlags(&eXori, cudaEventDisableTiming);
        cudaEventCreateWithFlags(&eSoft, cudaEventDisableTiming);
        cudaEventCreateWithFlags(&eEnd, cudaEventDisableTiming);
        s_init = true;
    }
    cudaStream_t sA = 0;

    dim3 tb(32, 8);
    const long long OSTR = 512LL * 3072;

    // ===== fork =====
    cudaEventRecord(eFork, sA);
    cudaStreamWaitEvent(sB, eFork, 0);

    // --- sA: x converts + Wkv transpose ---
    convert2_f16<<<dim3(2048, 2), 256, 0, sA>>>(x_cls, x_reg, Hp + HXCH,
                                                2048 * 256, 2 * Mi);
    transpose_convert2<<<dim3(64, 32, 2), tb, 0, sA>>>(W_kv_cls, W_kv_reg,
                                                       Hp + HWKH, 2048, 1024, 2 * Mi);
    cudaEventRecord(eX, sA);

    // --- sA: k projection (fp16) -> l2norm k ---
    g2<<<dim3(8, 32, 2), 128, SM64, sA>>>(
        Hp + HXCH, Hp + HWKH, nullptr,
        nullptr, Hp + HK16, nullptr, nullptr, 0.f, 0.f,
        1024, 1024, 1024, 1024,
        2, 2 * Mi, 0, 2 * Mi, 0, 2 * Mi, 0, 0, 0);
    l2norm_h16<<<dim3(2048, 2), 256, 0, sA>>>(Hp + HK16, Hp + HKH,
                                              1024, 1024, 2048 * 8, 2 * Mi, 2 * Mi);

    // --- sB: Wq/Wlin transposes + bias -> q projection (fp16) + l2norm q ---
    transpose_convert2<<<dim3(32, 32, 2), tb, 0, sB>>>(W_q_cls, W_q_reg,
                                                       Hp + HWQH, 1024, 1024, Mi);
    transpose_convert2<<<dim3(64, 64, 2), tb, 0, sB>>>(W_lin, W_lin_reg,
                                                       Hp + HWLH, 2048, 2048, 4 * Mi);
    copy_bias<<<8, 256, 0, sB>>>(b_lin, b_lin_reg, bias2);
    cudaStreamWaitEvent(sB, eX, 0);
    g2<<<dim3(8, 8, 2), 128, SM64, sB>>>(
        Hp + HXCH, Hp + HWQH, nullptr,
        nullptr, Hp + HQ16, nullptr, nullptr, 0.f, 0.f,
        1024, 1024, 1024, 1024,
        2, 2 * Mi, 0, Mi, 0, Mi / 2, 0, 0, 0);
    l2norm_h16<<<dim3(512, 2), 256, 0, sB>>>(Hp + HQ16, Hp + HQH,
                                             1024, 1024, 512 * 8, Mi / 2, Mi / 2);
    cudaEventRecord(eQ, sB);

    // --- sB: v projection (fp16 + xori mirror) + v norm + vT + sims(mask) ---
    g3<<<dim3(8, 32, 2), 128, SM64, sB>>>(
        Hp + HXCH, Hp + HWKH + Mi, nullptr,
        nullptr, Hp + HV16, Hp + HXCCH, nullptr, 0.f, 0.f,
        1024, 1024, 1024, 1024,
        2, 2 * Mi, 0, 2 * Mi, 0, 2 * Mi, 0, 0, Mi);
    cudaEventRecord(eXori, sB);
    l2norm_h16<<<dim3(2048, 2), 256, 0, sB>>>(Hp + HV16, Hp + HVNH,
                                              1024, 1024, 2048 * 8, 2 * Mi, 2 * Mi);
    transpose16<<<dim3(32, 64, 2), tb, 0, sB>>>(Hp + HV16, Hp + HVTH,
                                                1024, 2048, 2 * Mi, 2 * Mi);
    cudaEventRecord(eVT, sB);
    g4<<<dim3(16, 8, 2), 128, SM64, sB>>>(
        Hp + HVNH, Hp + HVNH, nullptr,
        nullptr, nullptr, nullptr, Mp, 0.75f, 0.99f,
        1024, 1024, 1024, 2048,
        2, 2 * Mi, 0, 2 * Mi, 0, Mi, 0, 0, 0);

    // --- sA: scores (needs q) -> softmax ---
    cudaStreamWaitEvent(sA, eQ, 0);
    g0<<<dim3(16, 8, 16), 128, SM64, sA>>>(
        Hp + HQH, Hp + HKH, nullptr,
        scc, nullptr, nullptr, nullptr, 0.f, 0.f,
        128, 1024, 1024, 2048,
        8, 128, Mi / 2, 128, 2 * Mi, Mi, 8 * Mi, 0, 0);
    softmax_combine2<<<dim3(512, 8), 256, 0, sA>>>(scc, scr, cls_score, Hp + HATH);
    cudaEventRecord(eSoft, sA);

    // --- sA: attn@v (needs vT) -> out-linears (needs xori) ---
    cudaStreamWaitEvent(sA, eVT, 0);
    g2<<<dim3(1, 8, 16), 128, SM64, sA>>>(
        Hp + HATH, Hp + HVTH, nullptr,
        nullptr, Hp + HXCCH, nullptr, nullptr, 0.f, 0.f,
        2048, 2048, 2048, 2048,
        8, Mi, 0, 128LL * 2048, 2 * Mi, 128, Mi, 0, 0);
    cudaStreamWaitEvent(sA, eXori, 0);
    g1<<<dim3(16, 8, 2), 128, SM64, sA>>>(
        Hp + HXCCH, Hp + HWLH, bias2,
        out + 1024, nullptr, nullptr, nullptr, 0.f, 0.f,
        2048, 2048, 2048, 3072,
        2, Mi, 0, 4 * Mi, 0, OSTR, 0, 2048, 0);

    // --- sB: mask_renorm (needs attn + masks) -> support ---
    cudaStreamWaitEvent(sB, eSoft, 0);
    mask_renorm<<<512, 256, 0, sB>>>(Hp + HATH, Mp, Mp + Mi, Hp + HS2H, Hp + HOWH);
    g0<<<dim3(8, 8, 2), 128, SM64, sB>>>(
        Hp + HS2H, Hp + HVTH, nullptr,
        out, nullptr, nullptr, nullptr, 0.f, 0.f,
        2048, 2048, 2048, 3072,
        2, Mi, 0, 2 * Mi, 0, OSTR, 0, 0, 0);
    cudaEventRecord(eEnd, sB);

    // ===== join =====
    cudaStreamWaitEvent(sA, eEnd, 0);
}